// round 16
// baseline (speedup 1.0000x reference)
#include <cuda_runtime.h>
#include <cuda_bf16.h>
#include <mma.h>
#include <cstdint>

using namespace nvcuda;

// ============================================================================
// FNO — single fused persistent kernel.
// Per 64-row chunk: encoder GEMM on tensor cores (bf16 3-product split,
// pre-split W1 in global) -> h in SMEM -> 4 fused FFT layers (2-for-1 real
// packing, branch-free butterflies, merged s1/pointwise/s1 stage) -> decoder.
// No h roundtrip through DRAM.
// ============================================================================

#define B_ROWS 262144
#define CHUNK_ROWS 64
#define N_CHUNKS (B_ROWS / CHUNK_ROWS)   // 4096
#define LDH 260                           // h smem row stride (floats)
#define LDA 72                            // a-split smem row stride (bf16)

// pre-split W1 (64 x 256) in bf16 hi/lo
__device__ __nv_bfloat16 g_w1hi[64 * 256];
__device__ __nv_bfloat16 g_w1lo[64 * 256];

static __device__ __forceinline__ float2 cmul(float2 a, float2 b) {
    return make_float2(fmaf(a.x, b.x, -a.y * b.y), fmaf(a.x, b.y, a.y * b.x));
}
static __device__ __forceinline__ float2 cadd(float2 a, float2 b) {
    return make_float2(a.x + b.x, a.y + b.y);
}
static __device__ __forceinline__ float2 csub(float2 a, float2 b) {
    return make_float2(a.x - b.x, a.y - b.y);
}
static __device__ __forceinline__ float2 conjf2(float2 a) {
    return make_float2(a.x, -a.y);
}

// ---------------------------------------------------------------------------
__global__ void split_w1_kernel(const float* __restrict__ W1) {
    int i = blockIdx.x * blockDim.x + threadIdx.x;   // 0..16383
    float v = W1[i];
    __nv_bfloat16 hi = __float2bfloat16(v);
    __nv_bfloat16 lo = __float2bfloat16(v - __bfloat162float(hi));
    g_w1hi[i] = hi;
    g_w1lo[i] = lo;
}

// ---------------------------------------------------------------------------
__global__ __launch_bounds__(256, 2) void fno_fused_kernel(
    const float* __restrict__ mu,  const float* __restrict__ xg,
    const float* __restrict__ b1,  const float* __restrict__ fw,
    const float* __restrict__ lw,  const float* __restrict__ W2,
    const float* __restrict__ b2,  float* __restrict__ out)
{
    // dynamic smem: h tile + a-split
    extern __shared__ char dyn_raw[];
    float* hsm = (float*)dyn_raw;                          // [64][LDH]
    __nv_bfloat16* ahi = (__nv_bfloat16*)(hsm + 64 * LDH); // [64][LDA]
    __nv_bfloat16* alo = ahi + 64 * LDA;

    // static smem: tables
    __shared__ float2 T[128];        // exp(-2*pi*i*k/256)
    __shared__ float2 WF[4][32];     // fwd cross-lane twiddles (s=16,8,4,2)
    __shared__ float2 WI[4][32];     // inv cross-lane pre-twiddles (s=2,4,8,16)
    __shared__ float2 pq[4][128];    // merged-stage coeffs per bitrev pair
    __shared__ float  lws[4][256];
    __shared__ float  W2s[256];
    __shared__ float  b1s[256];

    const int tid = threadIdx.x;
    if (tid < 128) {
        float s, c;
        sincospif((float)tid / 128.0f, &s, &c);
        T[tid] = make_float2(c, -s);
    }
    if (tid < 128) {   // branch-free cross-lane twiddle tables
        int st = tid >> 5, l = tid & 31;
        {
            int s = 16 >> st;
            float2 w = make_float2(1.f, 0.f);
            if (l & s) {
                int idx = (l & (s - 1)) * (128 / s);
                float sn, cs; sincospif((float)idx / 128.0f, &sn, &cs);
                w = make_float2(cs, -sn);
            }
            WF[st][l] = w;
        }
        {
            int s = 2 << st;
            float2 w = make_float2(1.f, 0.f);
            if (l & s) {
                int idx = (l & (s - 1)) * (128 / s);
                float sn, cs; sincospif((float)idx / 128.0f, &sn, &cs);
                w = make_float2(cs, sn);   // conj
            }
            WI[st][l] = w;
        }
    }
    for (int i = tid; i < 512; i += blockDim.x) {   // merged-stage coeffs
        int layer = i >> 7, t = i & 127;
        int pe = 2 * t, po = pe + 1;
        int me = __brev((unsigned)pe) >> 24;  me = (me <= 128) ? me : 256 - me;
        int mo = __brev((unsigned)po) >> 24;  mo = (mo <= 128) ? mo : 256 - mo;
        float we = fw[layer * 129 + me] * (1.0f / 256.0f);
        float wo = fw[layer * 129 + mo] * (1.0f / 256.0f);
        pq[layer][t] = make_float2(we + wo, we - wo);
    }
    for (int i = tid; i < 1024; i += blockDim.x) lws[i >> 8][i & 255] = lw[i];
    if (tid < 256) { W2s[tid] = W2[tid]; b1s[tid] = b1[tid]; }

    const float b2v  = b2[0];
    const int lane   = tid & 31;
    const int warp   = tid >> 5;
    const unsigned FULL = 0xFFFFFFFFu;

    for (int chunk = blockIdx.x; chunk < N_CHUNKS; chunk += gridDim.x) {
        __syncthreads();   // prev chunk's fft reads of hsm are done

        // ---- phase 1: load + split mu tile [64 x 64] ----
        for (int i = tid; i < 1024; i += 256) {
            int r  = i >> 4;
            int c4 = (i & 15) * 4;
            float4 a4 = *reinterpret_cast<const float4*>(
                mu + (size_t)(chunk * CHUNK_ROWS + r) * 64 + c4);
            float av[4] = {a4.x, a4.y, a4.z, a4.w};
#pragma unroll
            for (int m = 0; m < 4; m += 2) {
                __nv_bfloat16 h0 = __float2bfloat16(av[m]);
                __nv_bfloat16 h1 = __float2bfloat16(av[m + 1]);
                __nv_bfloat16 l0 = __float2bfloat16(av[m]     - __bfloat162float(h0));
                __nv_bfloat16 l1 = __float2bfloat16(av[m + 1] - __bfloat162float(h1));
                __nv_bfloat162 hh; hh.x = h0; hh.y = h1;
                __nv_bfloat162 ll; ll.x = l0; ll.y = l1;
                *reinterpret_cast<__nv_bfloat162*>(ahi + r * LDA + c4 + m) = hh;
                *reinterpret_cast<__nv_bfloat162*>(alo + r * LDA + c4 + m) = ll;
            }
        }
        __syncthreads();

        // ---- phase 2: wmma encoder -> raw h in smem ----
        {
            const int rstripe = (warp & 3) * 16;   // 0,16,32,48
            const int ct0     = (warp >> 2) * 8;   // 0 or 8

            wmma::fragment<wmma::matrix_a, 16, 16, 16, __nv_bfloat16,
                           wmma::row_major> fah[4], fal[4];
#pragma unroll
            for (int kt = 0; kt < 4; kt++) {
                wmma::load_matrix_sync(fah[kt], ahi + rstripe * LDA + kt * 16, LDA);
                wmma::load_matrix_sync(fal[kt], alo + rstripe * LDA + kt * 16, LDA);
            }
#pragma unroll
            for (int c = 0; c < 8; c++) {
                int ct = ct0 + c;
                wmma::fragment<wmma::accumulator, 16, 16, 16, float> acc;
                wmma::fill_fragment(acc, 0.f);
#pragma unroll
                for (int kt = 0; kt < 4; kt++) {
                    wmma::fragment<wmma::matrix_b, 16, 16, 16, __nv_bfloat16,
                                   wmma::row_major> fbh, fbl;
                    wmma::load_matrix_sync(fbh, g_w1hi + kt * 16 * 256 + ct * 16, 256);
                    wmma::load_matrix_sync(fbl, g_w1lo + kt * 16 * 256 + ct * 16, 256);
                    wmma::mma_sync(acc, fah[kt], fbh, acc);
                    wmma::mma_sync(acc, fal[kt], fbh, acc);
                    wmma::mma_sync(acc, fah[kt], fbl, acc);
                }
                wmma::store_matrix_sync(hsm + rstripe * LDH + ct * 16, acc, LDH,
                                        wmma::mem_row_major);
            }
        }
        __syncthreads();

        // ---- phase 3: FFT layers + decoder, 4 row-pairs per warp ----
#pragma unroll 1
        for (int pp = 0; pp < 4; pp++) {
            const int pl   = warp * 4 + pp;               // 0..31 in chunk
            const int row0 = chunk * CHUNK_ROWS + pl * 2;
            const int row1 = row0 + 1;

            float h0[8], h1[8];
#pragma unroll
            for (int j = 0; j < 8; j++) {   // bias + relu folded into load
                float bv = b1s[j * 32 + lane];
                h0[j] = fmaxf(hsm[(pl * 2)     * LDH + j * 32 + lane] + bv, 0.f);
                h1[j] = fmaxf(hsm[(pl * 2 + 1) * LDH + j * 32 + lane] + bv, 0.f);
            }
            const float xv0 = (lane < 3) ? xg[(size_t)row0 * 3 + lane] : 0.f;
            const float xv1 = (lane < 3) ? xg[(size_t)row1 * 3 + lane] : 0.f;

#pragma unroll
            for (int layer = 0; layer < 4; layer++) {
                // build d = [x0,x1,x2, h0..h252] for both rows (rotate by 3)
                float2 v[8];
                {
                    float s0[8], s1[8];
#pragma unroll
                    for (int j = 0; j < 8; j++) {
                        s0[j] = __shfl_sync(FULL, h0[j], (lane + 29) & 31);
                        s1[j] = __shfl_sync(FULL, h1[j], (lane + 29) & 31);
                    }
#pragma unroll
                    for (int j = 0; j < 8; j++) {
                        float d0, d1;
                        if (lane >= 3) { d0 = s0[j];             d1 = s1[j]; }
                        else           { d0 = (j == 0) ? xv0 : s0[j - 1];
                                         d1 = (j == 0) ? xv1 : s1[j - 1]; }
                        v[j] = make_float2(d0, d1);
                    }
                }

                // ================= forward DIF =================
#pragma unroll
                for (int j = 0; j < 4; j++) {   // L=256 (local)
                    float2 a = v[j], b = v[j + 4];
                    float2 W = T[j * 32 + lane];
                    v[j]     = cadd(a, b);
                    v[j + 4] = cmul(csub(a, b), W);
                }
#pragma unroll
                for (int p = 0; p < 4; p++) {   // L=128 (local)
                    int j = (p < 2) ? p : p + 2;
                    float2 a = v[j], b = v[j + 2];
                    float2 W = T[((j & 1) * 32 + lane) * 2];
                    v[j]     = cadd(a, b);
                    v[j + 2] = cmul(csub(a, b), W);
                }
                {                               // L=64 (local)
                    float2 W = T[lane * 4];
#pragma unroll
                    for (int j = 0; j < 8; j += 2) {
                        float2 a = v[j], b = v[j + 1];
                        v[j]     = cadd(a, b);
                        v[j + 1] = cmul(csub(a, b), W);
                    }
                }
                // cross-lane stages s = 16,8,4,2 (branch-free)
#pragma unroll
                for (int st = 0; st < 4; st++) {
                    const int s = 16 >> st;
                    const float sgn = (lane & s) ? -1.f : 1.f;
                    const float2 W = WF[st][lane];
#pragma unroll
                    for (int j = 0; j < 8; j++) {
                        float ox = __shfl_xor_sync(FULL, v[j].x, s);
                        float oy = __shfl_xor_sync(FULL, v[j].y, s);
                        float txx = fmaf(sgn, v[j].x, ox);
                        float tyy = fmaf(sgn, v[j].y, oy);
                        v[j] = cmul(make_float2(txx, tyy), W);
                    }
                }

                // MERGED fwd-s1 o pointwise o inv-s1: out = p*own + q*neigh
#pragma unroll
                for (int j = 0; j < 8; j++) {
                    float2 PQ = pq[layer][j * 16 + (lane >> 1)];
                    float nx = __shfl_xor_sync(FULL, v[j].x, 1);
                    float ny = __shfl_xor_sync(FULL, v[j].y, 1);
                    v[j].x = fmaf(PQ.x, v[j].x, PQ.y * nx);
                    v[j].y = fmaf(PQ.x, v[j].y, PQ.y * ny);
                }

                // ================= inverse DIT =================
#pragma unroll
                for (int st = 0; st < 4; st++) {   // s = 2,4,8,16
                    const int s = 2 << st;
                    const float sgn = (lane & s) ? -1.f : 1.f;
                    const float2 W = WI[st][lane];
#pragma unroll
                    for (int j = 0; j < 8; j++) {
                        float2 u = cmul(v[j], W);   // identity on lower lanes
                        float ox = __shfl_xor_sync(FULL, u.x, s);
                        float oy = __shfl_xor_sync(FULL, u.y, s);
                        v[j].x = fmaf(sgn, u.x, ox);
                        v[j].y = fmaf(sgn, u.y, oy);
                    }
                }
                {                               // L=64 (local)
                    float2 W = conjf2(T[lane * 4]);
#pragma unroll
                    for (int j = 0; j < 8; j += 2) {
                        float2 u = v[j];
                        float2 t2 = cmul(v[j + 1], W);
                        v[j]     = cadd(u, t2);
                        v[j + 1] = csub(u, t2);
                    }
                }
#pragma unroll
                for (int p = 0; p < 4; p++) {   // L=128 (local)
                    int j = (p < 2) ? p : p + 2;
                    float2 W = conjf2(T[((j & 1) * 32 + lane) * 2]);
                    float2 u = v[j];
                    float2 t2 = cmul(v[j + 2], W);
                    v[j]     = cadd(u, t2);
                    v[j + 2] = csub(u, t2);
                }
#pragma unroll
                for (int j = 0; j < 4; j++) {   // L=256 (local)
                    float2 W = conjf2(T[j * 32 + lane]);
                    float2 u = v[j];
                    float2 t2 = cmul(v[j + 4], W);
                    v[j]     = cadd(u, t2);
                    v[j + 4] = csub(u, t2);
                }

                // residual + relu
#pragma unroll
                for (int j = 0; j < 8; j++) {
                    float lwv = lws[layer][j * 32 + lane];
                    h0[j] = fmaxf(fmaf(lwv, h0[j], v[j].x), 0.f);
                    h1[j] = fmaxf(fmaf(lwv, h1[j], v[j].y), 0.f);
                }
            }

            // ---- decoder ----
            float a0 = 0.f, a1 = 0.f;
#pragma unroll
            for (int j = 0; j < 8; j++) {
                float w = W2s[j * 32 + lane];
                a0 = fmaf(h0[j], w, a0);
                a1 = fmaf(h1[j], w, a1);
            }
#pragma unroll
            for (int s = 16; s; s >>= 1) {
                a0 += __shfl_xor_sync(FULL, a0, s);
                a1 += __shfl_xor_sync(FULL, a1, s);
            }
            if (lane == 0) {
                out[row0] = a0 + b2v;
                out[row1] = a1 + b2v;
            }
        }
    }
}

static const int FUSED_DYN_SMEM =
    64 * LDH * (int)sizeof(float) +                    // h tile
    2 * 64 * LDA * (int)sizeof(__nv_bfloat16);         // a-split hi/lo

// ---------------------------------------------------------------------------
extern "C" void kernel_launch(void* const* d_in, const int* in_sizes, int n_in,
                              void* d_out, int out_size)
{
    const float* mu = (const float*)d_in[0];   // [262144, 64]
    const float* x  = (const float*)d_in[1];   // [262144, 3]
    const float* W1 = (const float*)d_in[2];   // [64, 256]
    const float* b1 = (const float*)d_in[3];   // [256]
    const float* fw = (const float*)d_in[4];   // [4, 129]
    const float* lw = (const float*)d_in[5];   // [4, 256]
    const float* W2 = (const float*)d_in[6];   // [256, 1]
    const float* b2 = (const float*)d_in[7];   // [1]
    float* out = (float*)d_out;                // [262144, 1]

    split_w1_kernel<<<64, 256>>>(W1);

    cudaFuncSetAttribute(fno_fused_kernel,
                         cudaFuncAttributeMaxDynamicSharedMemorySize,
                         FUSED_DYN_SMEM);
    fno_fused_kernel<<<592, 256, FUSED_DYN_SMEM>>>(
        mu, x, b1, fw, lw, W2, b2, out);
}